// round 1
// baseline (speedup 1.0000x reference)
#include <cuda_runtime.h>
#include <math.h>

// Shapes fixed by the reference problem.
#define B_DIM 32
#define T_DIM 8192
#define C_DIM 256
#define CHUNKS 32              // T split across blocks
#define TCHUNK (T_DIM / CHUNKS)  // 256 t per chunk
#define TLANES 4               // t-lanes per block
#define ITERS (TCHUNK / TLANES)  // 64 sequential t-steps per thread
#define CG 64                  // c-groups (of 4 channels) per block
#define NSTAT 5                // S1, S2, S3, S4, Sp
#define EPSF 1e-6

// Partial sums: [B][CHUNKS][CG][NSTAT*4]  (4 = channels within float4 group)
__device__ float g_scratch[B_DIM * CHUNKS * CG * NSTAT * 4];

__global__ __launch_bounds__(256, 4)
void hom_pass1(const float* __restrict__ x, const float* __restrict__ p)
{
    const int chunk = blockIdx.x;
    const int b     = blockIdx.y;
    const int tid   = threadIdx.x;
    const int cg    = tid & 63;      // 0..63 channel group
    const int tlane = tid >> 6;      // 0..3

    const float pv = p[0];
    const bool p_is_one = (pv == 1.0f);

    // base element offset: x[b, chunk*TCHUNK + tlane, cg*4]
    const float* ptr = x + ((size_t)b * T_DIM + (size_t)chunk * TCHUNK + tlane) * C_DIM
                         + cg * 4;
    const size_t step = (size_t)TLANES * C_DIM;   // advance 4 t-rows

    float s1x=0.f,s1y=0.f,s1z=0.f,s1w=0.f;
    float s2x=0.f,s2y=0.f,s2z=0.f,s2w=0.f;
    float s3x=0.f,s3y=0.f,s3z=0.f,s3w=0.f;
    float s4x=0.f,s4y=0.f,s4z=0.f,s4w=0.f;
    float spx=0.f,spy=0.f,spz=0.f,spw=0.f;

    if (p_is_one) {
        #pragma unroll 8
        for (int i = 0; i < ITERS; ++i) {
            const float4 v = *reinterpret_cast<const float4*>(ptr + (size_t)i * step);
            float x2;
            x2 = v.x*v.x; s1x += v.x; s2x += x2; s3x += x2*v.x; s4x += x2*x2;
            x2 = v.y*v.y; s1y += v.y; s2y += x2; s3y += x2*v.y; s4y += x2*x2;
            x2 = v.z*v.z; s1z += v.z; s2z += x2; s3z += x2*v.z; s4z += x2*x2;
            x2 = v.w*v.w; s1w += v.w; s2w += x2; s3w += x2*v.w; s4w += x2*x2;
        }
        spx = s1x; spy = s1y; spz = s1z; spw = s1w;   // mean(x^1) == mean(x)
    } else {
        #pragma unroll 4
        for (int i = 0; i < ITERS; ++i) {
            const float4 v = *reinterpret_cast<const float4*>(ptr + (size_t)i * step);
            float x2;
            x2 = v.x*v.x; s1x += v.x; s2x += x2; s3x += x2*v.x; s4x += x2*x2; spx += __powf(v.x, pv);
            x2 = v.y*v.y; s1y += v.y; s2y += x2; s3y += x2*v.y; s4y += x2*x2; spy += __powf(v.y, pv);
            x2 = v.z*v.z; s1z += v.z; s2z += x2; s3z += x2*v.z; s4z += x2*x2; spz += __powf(v.z, pv);
            x2 = v.w*v.w; s1w += v.w; s2w += x2; s3w += x2*v.w; s4w += x2*x2; spw += __powf(v.w, pv);
        }
    }

    // Reduce over the 4 t-lanes via shared memory, then write partials.
    // Layout: sm[tlane][cg][20]
    __shared__ float sm[TLANES][CG][NSTAT * 4];
    float* dst = sm[tlane][cg];
    dst[ 0]=s1x; dst[ 1]=s1y; dst[ 2]=s1z; dst[ 3]=s1w;
    dst[ 4]=s2x; dst[ 5]=s2y; dst[ 6]=s2z; dst[ 7]=s2w;
    dst[ 8]=s3x; dst[ 9]=s3y; dst[10]=s3z; dst[11]=s3w;
    dst[12]=s4x; dst[13]=s4y; dst[14]=s4z; dst[15]=s4w;
    dst[16]=spx; dst[17]=spy; dst[18]=spz; dst[19]=spw;
    __syncthreads();

    // 256 threads cover 64*20 = 1280 sums: 5 each.
    float* out = g_scratch + ((size_t)(b * CHUNKS + chunk) * CG) * (NSTAT * 4);
    #pragma unroll
    for (int k = 0; k < 5; ++k) {
        const int idx = tid + k * 256;     // 0..1279
        const int g  = idx / (NSTAT * 4);  // c-group
        const int j  = idx % (NSTAT * 4);  // stat*4 + sub-channel
        const float v = sm[0][g][j] + sm[1][g][j] + sm[2][g][j] + sm[3][g][j];
        out[g * (NSTAT * 4) + j] = v;
    }
}

__global__ __launch_bounds__(256, 4)
void hom_pass2(float* __restrict__ out)
{
    const int tid = blockIdx.x * blockDim.x + threadIdx.x;  // 0 .. B*C-1
    if (tid >= B_DIM * C_DIM) return;
    const int b   = tid / C_DIM;
    const int c   = tid % C_DIM;
    const int cg  = c >> 2;
    const int sub = c & 3;

    double S1=0.0, S2=0.0, S3=0.0, S4=0.0, Sp=0.0;
    #pragma unroll 4
    for (int chunk = 0; chunk < CHUNKS; ++chunk) {
        const float* src = g_scratch
            + ((size_t)(b * CHUNKS + chunk) * CG + cg) * (NSTAT * 4);
        S1 += (double)src[ 0 + sub];
        S2 += (double)src[ 4 + sub];
        S3 += (double)src[ 8 + sub];
        S4 += (double)src[12 + sub];
        Sp += (double)src[16 + sub];
    }

    const double invT = 1.0 / (double)T_DIM;
    const double mu  = S1 * invT;
    const double m2r = S2 * invT;   // E[x^2]
    const double m3r = S3 * invT;   // E[x^3]
    const double m4r = S4 * invT;   // E[x^4]
    const double grp = Sp * invT;

    const double mu2 = mu * mu;
    const double var = m2r - mu2;
    const double m3  = m3r - 3.0 * mu * m2r + 2.0 * mu * mu2;
    const double m4  = m4r - 4.0 * mu * m3r + 6.0 * mu2 * m2r - 3.0 * mu2 * mu2;

    const double ve   = var + (double)EPSF;
    const double std_ = sqrt(ve);
    const double skew = m3 / (ve * std_);   // std^3
    const double kurt = m4 / (ve * ve);     // std^4

    float* o = out + (size_t)b * (4 * C_DIM);
    o[c]             = (float)grp;
    o[C_DIM + c]     = (float)var;
    o[2 * C_DIM + c] = (float)skew;
    o[3 * C_DIM + c] = (float)kurt;
}

extern "C" void kernel_launch(void* const* d_in, const int* in_sizes, int n_in,
                              void* d_out, int out_size)
{
    const float* x = (const float*)d_in[0];
    const float* p = (const float*)d_in[1];
    float* out = (float*)d_out;

    dim3 grid1(CHUNKS, B_DIM);
    hom_pass1<<<grid1, 256>>>(x, p);

    const int n2 = B_DIM * C_DIM;
    hom_pass2<<<(n2 + 255) / 256, 256>>>(out);
}

// round 2
// speedup vs baseline: 1.3242x; 1.3242x over previous
#include <cuda_runtime.h>
#include <math.h>

// Shapes fixed by the reference problem.
#define B_DIM 32
#define T_DIM 8192
#define C_DIM 256
#define CHUNKS 32              // T split across blocks
#define TCHUNK (T_DIM / CHUNKS)  // 256 t per chunk
#define TLANES 4               // t-lanes per block
#define ITERS (TCHUNK / TLANES)  // 64 sequential t-steps per thread
#define CG 64                  // c-groups (of 4 channels) per block
#define NSTAT 5                // S1, S2, S3, S4, Sp
#define EPSF 1e-6

// Partial sums, coalesced layout: [NSTAT][CHUNKS][B][C]
__device__ float g_scratch[NSTAT * CHUNKS * B_DIM * C_DIM];

__global__ __launch_bounds__(256, 4)
void hom_pass1(const float* __restrict__ x, const float* __restrict__ p)
{
    const int chunk = blockIdx.x;
    const int b     = blockIdx.y;
    const int tid   = threadIdx.x;
    const int cg    = tid & 63;      // 0..63 channel group
    const int tlane = tid >> 6;      // 0..3

    const float pv = p[0];
    const bool p_is_one = (pv == 1.0f);

    // base element offset: x[b, chunk*TCHUNK + tlane, cg*4]
    const float* ptr = x + ((size_t)b * T_DIM + (size_t)chunk * TCHUNK + tlane) * C_DIM
                         + cg * 4;
    const size_t step = (size_t)TLANES * C_DIM;   // advance 4 t-rows

    float s1x=0.f,s1y=0.f,s1z=0.f,s1w=0.f;
    float s2x=0.f,s2y=0.f,s2z=0.f,s2w=0.f;
    float s3x=0.f,s3y=0.f,s3z=0.f,s3w=0.f;
    float s4x=0.f,s4y=0.f,s4z=0.f,s4w=0.f;
    float spx=0.f,spy=0.f,spz=0.f,spw=0.f;

    if (p_is_one) {
        #pragma unroll 8
        for (int i = 0; i < ITERS; ++i) {
            const float4 v = *reinterpret_cast<const float4*>(ptr + (size_t)i * step);
            float x2;
            x2 = v.x*v.x; s1x += v.x; s2x += x2; s3x += x2*v.x; s4x += x2*x2;
            x2 = v.y*v.y; s1y += v.y; s2y += x2; s3y += x2*v.y; s4y += x2*x2;
            x2 = v.z*v.z; s1z += v.z; s2z += x2; s3z += x2*v.z; s4z += x2*x2;
            x2 = v.w*v.w; s1w += v.w; s2w += x2; s3w += x2*v.w; s4w += x2*x2;
        }
        spx = s1x; spy = s1y; spz = s1z; spw = s1w;   // mean(x^1) == mean(x)
    } else {
        #pragma unroll 4
        for (int i = 0; i < ITERS; ++i) {
            const float4 v = *reinterpret_cast<const float4*>(ptr + (size_t)i * step);
            float x2;
            x2 = v.x*v.x; s1x += v.x; s2x += x2; s3x += x2*v.x; s4x += x2*x2; spx += __powf(v.x, pv);
            x2 = v.y*v.y; s1y += v.y; s2y += x2; s3y += x2*v.y; s4y += x2*x2; spy += __powf(v.y, pv);
            x2 = v.z*v.z; s1z += v.z; s2z += x2; s3z += x2*v.z; s4z += x2*x2; spz += __powf(v.z, pv);
            x2 = v.w*v.w; s1w += v.w; s2w += x2; s3w += x2*v.w; s4w += x2*x2; spw += __powf(v.w, pv);
        }
    }

    // Stage per-thread sums in shared: sm[tlane][cg][stat*4+sub]
    __shared__ float sm[TLANES][CG][NSTAT * 4];
    float* dst = sm[tlane][cg];
    dst[ 0]=s1x; dst[ 1]=s1y; dst[ 2]=s1z; dst[ 3]=s1w;
    dst[ 4]=s2x; dst[ 5]=s2y; dst[ 6]=s2z; dst[ 7]=s2w;
    dst[ 8]=s3x; dst[ 9]=s3y; dst[10]=s3z; dst[11]=s3w;
    dst[12]=s4x; dst[13]=s4y; dst[14]=s4z; dst[15]=s4w;
    dst[16]=spx; dst[17]=spy; dst[18]=spz; dst[19]=spw;
    __syncthreads();

    // Thread tid owns channel c = tid. Reduce the 4 t-lanes and write the
    // coalesced [stat][chunk][b][c] layout (consecutive tid -> consecutive addr).
    const int c   = tid;
    const int cgq = c >> 2;
    const int sub = c & 3;
    #pragma unroll
    for (int stat = 0; stat < NSTAT; ++stat) {
        const int j = stat * 4 + sub;
        const float v = sm[0][cgq][j] + sm[1][cgq][j] + sm[2][cgq][j] + sm[3][cgq][j];
        g_scratch[((size_t)(stat * CHUNKS + chunk) * B_DIM + b) * C_DIM + c] = v;
    }
}

__global__ __launch_bounds__(256, 8)
void hom_pass2(float* __restrict__ out)
{
    const int tid = blockIdx.x * blockDim.x + threadIdx.x;  // 0 .. B*C-1
    if (tid >= B_DIM * C_DIM) return;
    const int b = tid >> 8;
    const int c = tid & 255;

    // Accumulate 32 chunk partials per stat; fully coalesced loads, L2-hot.
    float S[NSTAT];
    #pragma unroll
    for (int s = 0; s < NSTAT; ++s) S[s] = 0.f;

    const size_t bc = (size_t)b * C_DIM + c;
    #pragma unroll 8
    for (int chunk = 0; chunk < CHUNKS; ++chunk) {
        #pragma unroll
        for (int s = 0; s < NSTAT; ++s) {
            S[s] += g_scratch[((size_t)(s * CHUNKS + chunk) * B_DIM * C_DIM) + bc];
        }
    }

    const double invT = 1.0 / (double)T_DIM;
    const double mu  = (double)S[0] * invT;
    const double m2r = (double)S[1] * invT;   // E[x^2]
    const double m3r = (double)S[2] * invT;   // E[x^3]
    const double m4r = (double)S[3] * invT;   // E[x^4]
    const double grp = (double)S[4] * invT;

    const double mu2 = mu * mu;
    const double var = m2r - mu2;
    const double m3  = m3r - 3.0 * mu * m2r + 2.0 * mu * mu2;
    const double m4  = m4r - 4.0 * mu * m3r + 6.0 * mu2 * m2r - 3.0 * mu2 * mu2;

    const double ve   = var + (double)EPSF;
    const double std_ = sqrt(ve);
    const double skew = m3 / (ve * std_);   // std^3
    const double kurt = m4 / (ve * ve);     // std^4

    float* o = out + (size_t)b * (4 * C_DIM);
    o[c]             = (float)grp;
    o[C_DIM + c]     = (float)var;
    o[2 * C_DIM + c] = (float)skew;
    o[3 * C_DIM + c] = (float)kurt;
}

extern "C" void kernel_launch(void* const* d_in, const int* in_sizes, int n_in,
                              void* d_out, int out_size)
{
    const float* x = (const float*)d_in[0];
    const float* p = (const float*)d_in[1];
    float* out = (float*)d_out;

    dim3 grid1(CHUNKS, B_DIM);
    hom_pass1<<<grid1, 256>>>(x, p);

    const int n2 = B_DIM * C_DIM;
    hom_pass2<<<(n2 + 255) / 256, 256>>>(out);
}

// round 3
// speedup vs baseline: 1.3717x; 1.0359x over previous
#include <cuda_runtime.h>
#include <math.h>

// Shapes fixed by the reference problem.
#define B_DIM 32
#define T_DIM 8192
#define C_DIM 256
#define CHUNKS 32                // T split across blocks
#define TCHUNK (T_DIM / CHUNKS)  // 256 t per chunk
#define TLANES 4                 // t-lanes per block
#define ITERS (TCHUNK / TLANES)  // 64 sequential t-steps per thread
#define CG 64                    // c-groups (of 4 channels) per block
#define NSTAT 5                  // S1, S2, S3, S4, Sp
#define EPSF 1e-6

// Partial sums, coalesced layout: [NSTAT][CHUNKS][B][C]
__device__ float g_scratch[NSTAT * CHUNKS * B_DIM * C_DIM];
// Completion counters, one per batch. Zero-initialized; reset by last block.
__device__ int g_count[B_DIM];

// ---- packed f32x2 helpers --------------------------------------------------
__device__ __forceinline__ unsigned long long mul2(unsigned long long a,
                                                   unsigned long long b) {
    unsigned long long d;
    asm("mul.rn.f32x2 %0, %1, %2;" : "=l"(d) : "l"(a), "l"(b));
    return d;
}
__device__ __forceinline__ unsigned long long add2(unsigned long long a,
                                                   unsigned long long b) {
    unsigned long long d;
    asm("add.rn.f32x2 %0, %1, %2;" : "=l"(d) : "l"(a), "l"(b));
    return d;
}
__device__ __forceinline__ unsigned long long fma2(unsigned long long a,
                                                   unsigned long long b,
                                                   unsigned long long c) {
    unsigned long long d;
    asm("fma.rn.f32x2 %0, %1, %2, %3;" : "=l"(d) : "l"(a), "l"(b), "l"(c));
    return d;
}
__device__ __forceinline__ unsigned long long pack2(float lo, float hi) {
    unsigned long long r;
    asm("mov.b64 %0, {%1, %2};" : "=l"(r) : "f"(lo), "f"(hi));
    return r;
}
__device__ __forceinline__ void unpack2(unsigned long long v, float& lo, float& hi) {
    asm("mov.b64 {%0, %1}, %2;" : "=f"(lo), "=f"(hi) : "l"(v));
}
// ----------------------------------------------------------------------------

__global__ __launch_bounds__(256, 4)
void hom_fused(const float* __restrict__ x, const float* __restrict__ p,
               float* __restrict__ out)
{
    const int chunk = blockIdx.x;
    const int b     = blockIdx.y;
    const int tid   = threadIdx.x;
    const int cg    = tid & 63;      // 0..63 channel group
    const int tlane = tid >> 6;      // 0..3

    const float pv = p[0];
    const bool p_is_one = (pv == 1.0f);

    // base element offset: x[b, chunk*TCHUNK + tlane, cg*4]
    const float* ptr = x + ((size_t)b * T_DIM + (size_t)chunk * TCHUNK + tlane) * C_DIM
                         + cg * 4;
    const size_t step = (size_t)TLANES * C_DIM;   // advance 4 t-rows (in floats)

    // Pair accumulators: *xy holds channels {c,c+1}, *zw holds {c+2,c+3}.
    unsigned long long s1xy = 0ull, s1zw = 0ull;
    unsigned long long s2xy = 0ull, s2zw = 0ull;
    unsigned long long s3xy = 0ull, s3zw = 0ull;
    unsigned long long s4xy = 0ull, s4zw = 0ull;
    unsigned long long spxy = 0ull, spzw = 0ull;

    if (p_is_one) {
        #pragma unroll 8
        for (int i = 0; i < ITERS; ++i) {
            const ulonglong2 v = *reinterpret_cast<const ulonglong2*>(
                ptr + (size_t)i * step);
            const unsigned long long vxy = v.x, vzw = v.y;
            const unsigned long long x2xy = mul2(vxy, vxy);
            const unsigned long long x2zw = mul2(vzw, vzw);
            s1xy = add2(s1xy, vxy);          s1zw = add2(s1zw, vzw);
            s2xy = add2(s2xy, x2xy);         s2zw = add2(s2zw, x2zw);
            s3xy = fma2(x2xy, vxy, s3xy);    s3zw = fma2(x2zw, vzw, s3zw);
            s4xy = fma2(x2xy, x2xy, s4xy);   s4zw = fma2(x2zw, x2zw, s4zw);
        }
        spxy = s1xy; spzw = s1zw;   // mean(x^1) == mean(x)
    } else {
        // Generic power path (never taken for this dataset's p == 1).
        float a1x=0,a1y=0,a1z=0,a1w=0, a2x=0,a2y=0,a2z=0,a2w=0;
        float a3x=0,a3y=0,a3z=0,a3w=0, a4x=0,a4y=0,a4z=0,a4w=0;
        float apx=0,apy=0,apz=0,apw=0;
        for (int i = 0; i < ITERS; ++i) {
            const float4 v = *reinterpret_cast<const float4*>(ptr + (size_t)i * step);
            float x2;
            x2=v.x*v.x; a1x+=v.x; a2x+=x2; a3x+=x2*v.x; a4x+=x2*x2; apx+=__powf(v.x,pv);
            x2=v.y*v.y; a1y+=v.y; a2y+=x2; a3y+=x2*v.y; a4y+=x2*x2; apy+=__powf(v.y,pv);
            x2=v.z*v.z; a1z+=v.z; a2z+=x2; a3z+=x2*v.z; a4z+=x2*x2; apz+=__powf(v.z,pv);
            x2=v.w*v.w; a1w+=v.w; a2w+=x2; a3w+=x2*v.w; a4w+=x2*x2; apw+=__powf(v.w,pv);
        }
        s1xy=pack2(a1x,a1y); s1zw=pack2(a1z,a1w);
        s2xy=pack2(a2x,a2y); s2zw=pack2(a2z,a2w);
        s3xy=pack2(a3x,a3y); s3zw=pack2(a3z,a3w);
        s4xy=pack2(a4x,a4y); s4zw=pack2(a4z,a4w);
        spxy=pack2(apx,apy); spzw=pack2(apz,apw);
    }

    // Stage per-thread sums in shared: sm[tlane][cg][stat*4+sub]
    __shared__ float sm[TLANES][CG][NSTAT * 4];
    {
        float* dst = sm[tlane][cg];
        unpack2(s1xy, dst[ 0], dst[ 1]); unpack2(s1zw, dst[ 2], dst[ 3]);
        unpack2(s2xy, dst[ 4], dst[ 5]); unpack2(s2zw, dst[ 6], dst[ 7]);
        unpack2(s3xy, dst[ 8], dst[ 9]); unpack2(s3zw, dst[10], dst[11]);
        unpack2(s4xy, dst[12], dst[13]); unpack2(s4zw, dst[14], dst[15]);
        unpack2(spxy, dst[16], dst[17]); unpack2(spzw, dst[18], dst[19]);
    }
    __syncthreads();

    // Thread tid owns channel c = tid. Reduce the 4 t-lanes and write the
    // coalesced [stat][chunk][b][c] partials.
    {
        const int c   = tid;
        const int cgq = c >> 2;
        const int sub = c & 3;
        #pragma unroll
        for (int stat = 0; stat < NSTAT; ++stat) {
            const int j = stat * 4 + sub;
            const float v = sm[0][cgq][j] + sm[1][cgq][j]
                          + sm[2][cgq][j] + sm[3][cgq][j];
            g_scratch[((size_t)(stat * CHUNKS + chunk) * B_DIM + b) * C_DIM + c] = v;
        }
    }

    // ---- last-block-done final reduction for this batch ----
    __threadfence();              // make this block's partials globally visible
    __syncthreads();
    __shared__ int is_last;
    if (tid == 0) {
        const int old = atomicAdd(&g_count[b], 1);
        is_last = (old == CHUNKS - 1);
    }
    __syncthreads();

    if (is_last) {
        __threadfence();          // acquire: see all other blocks' partials
        const int c = tid;        // one channel per thread

        float S[NSTAT];
        #pragma unroll
        for (int s = 0; s < NSTAT; ++s) S[s] = 0.f;

        const size_t bc = (size_t)b * C_DIM + c;
        #pragma unroll 8
        for (int ch = 0; ch < CHUNKS; ++ch) {
            #pragma unroll
            for (int s = 0; s < NSTAT; ++s) {
                S[s] += g_scratch[((size_t)(s * CHUNKS + ch) * B_DIM * C_DIM) + bc];
            }
        }

        const double invT = 1.0 / (double)T_DIM;
        const double mu  = (double)S[0] * invT;
        const double m2r = (double)S[1] * invT;   // E[x^2]
        const double m3r = (double)S[2] * invT;   // E[x^3]
        const double m4r = (double)S[3] * invT;   // E[x^4]
        const double grp = (double)S[4] * invT;

        const double mu2 = mu * mu;
        const double var = m2r - mu2;
        const double m3  = m3r - 3.0 * mu * m2r + 2.0 * mu * mu2;
        const double m4  = m4r - 4.0 * mu * m3r + 6.0 * mu2 * m2r - 3.0 * mu2 * mu2;

        const double ve   = var + (double)EPSF;
        const double std_ = sqrt(ve);
        const double skew = m3 / (ve * std_);   // std^3
        const double kurt = m4 / (ve * ve);     // std^4

        float* o = out + (size_t)b * (4 * C_DIM);
        o[c]             = (float)grp;
        o[C_DIM + c]     = (float)var;
        o[2 * C_DIM + c] = (float)skew;
        o[3 * C_DIM + c] = (float)kurt;

        if (tid == 0) g_count[b] = 0;   // reset for next graph replay
    }
}

extern "C" void kernel_launch(void* const* d_in, const int* in_sizes, int n_in,
                              void* d_out, int out_size)
{
    const float* x = (const float*)d_in[0];
    const float* p = (const float*)d_in[1];
    float* out = (float*)d_out;

    dim3 grid(CHUNKS, B_DIM);
    hom_fused<<<grid, 256>>>(x, p, out);
}